// round 6
// baseline (speedup 1.0000x reference)
#include <cuda_runtime.h>
#include <cuda_bf16.h>
#include <cstdint>

#define VOCAB  8000
#define HIDDEN 256
#define BATCH  32
#define SEQ    256
#define M_OUT  (SEQ*BATCH)      // 8192
#define N_OUT  VOCAB            // 8000
#define K_OUT  HIDDEN           // 256

// Scratch: Y (seq, batch, hidden) = hidden states for all steps (8 MB).
__device__ float g_Y[SEQ * BATCH * HIDDEN];

// ---------------------------------------------------------------------------
// Kernel 1: recurrence. One block per batch element (independent chains).
// h double-buffered in shared memory; W_hh streamed from L1 (L2-resident,
// 256 KB, identical across blocks). fp32 throughout (recurrence precision:
// bf16 weights would give ~3e-3 output error, over the 1e-3 gate).
// ---------------------------------------------------------------------------
__global__ __launch_bounds__(HIDDEN, 1)
void rnn_recurrence(const int* __restrict__ X,
                    const float* __restrict__ h0,
                    const float* __restrict__ W_ih,
                    const float* __restrict__ b_ih,
                    const float* __restrict__ W_hh,
                    const float* __restrict__ b_hh,
                    float* __restrict__ hlast)   // may be null
{
    __shared__ float sh[2][HIDDEN];
    const int b = blockIdx.x;
    const int j = threadIdx.x;

    sh[0][j] = h0[b * HIDDEN + j];
    const float bias = b_ih[j] + b_hh[j];
    const float4* __restrict__ wrow =
        reinterpret_cast<const float4*>(W_hh + (size_t)j * HIDDEN);
    const float* __restrict__ wih_row = W_ih + (size_t)j * VOCAB;
    const int* __restrict__ xrow = X + b * SEQ;
    __syncthreads();

    int cur = 0;
    int idx = xrow[0];
    for (int t = 0; t < SEQ; ++t) {
        float a0 = 0.f, a1 = 0.f, a2 = 0.f, a3 = 0.f;
        const float4* hv = reinterpret_cast<const float4*>(sh[cur]);
        #pragma unroll 16
        for (int k = 0; k < HIDDEN / 4; ++k) {
            const float4 w  = wrow[k];
            const float4 h4 = hv[k];
            a0 = fmaf(w.x, h4.x, a0);
            a1 = fmaf(w.y, h4.y, a1);
            a2 = fmaf(w.z, h4.z, a2);
            a3 = fmaf(w.w, h4.w, a3);
        }
        float acc = wih_row[idx] + bias + ((a0 + a1) + (a2 + a3));
        if (t + 1 < SEQ) idx = xrow[t + 1];   // prefetch next gather index
        const float hn = tanhf(acc);
        g_Y[((size_t)t * BATCH + b) * HIDDEN + j] = hn;
        sh[cur ^ 1][j] = hn;
        __syncthreads();
        cur ^= 1;
    }
    if (hlast) hlast[b * HIDDEN + j] = sh[cur][j];
}

// ---------------------------------------------------------------------------
// Kernel 2: out = Y @ W_out^T + b_out via tf32 mma.sync (m16n8k8).
// Block tile 128(M) x 64(N), BK=32.  8 warps: 4(M) x 2(N), warp tile 32x32.
// Smem padded to stride 36 words -> conflict-free fragment loads.
// ---------------------------------------------------------------------------
__device__ __forceinline__ unsigned f2tf32(float x) {
    unsigned r;
    asm("cvt.rna.tf32.f32 %0, %1;" : "=r"(r) : "f"(x));
    return r;
}

__device__ __forceinline__ void mma_tf32(float& d0, float& d1, float& d2, float& d3,
                                         unsigned a0, unsigned a1, unsigned a2, unsigned a3,
                                         unsigned b0, unsigned b1)
{
    asm volatile(
        "mma.sync.aligned.m16n8k8.row.col.f32.tf32.tf32.f32 "
        "{%0,%1,%2,%3}, {%4,%5,%6,%7}, {%8,%9}, {%0,%1,%2,%3};\n"
        : "+f"(d0), "+f"(d1), "+f"(d2), "+f"(d3)
        : "r"(a0), "r"(a1), "r"(a2), "r"(a3), "r"(b0), "r"(b1));
}

#define BM 128
#define BN 64
#define BK 32
#define PAD_STRIDE 36   // BK + 4 words

__global__ __launch_bounds__(256, 2)
void out_gemm(const float* __restrict__ W_out,
              const float* __restrict__ b_out,
              float* __restrict__ out)
{
    __shared__ unsigned As[BM * PAD_STRIDE];  // tf32 bits
    __shared__ unsigned Bs[BN * PAD_STRIDE];

    const int tid  = threadIdx.x;
    const int lane = tid & 31;
    const int warp = tid >> 5;
    const int g = lane >> 2;       // group id 0..7
    const int t = lane & 3;        // thread-in-group 0..3
    const int warpM = warp >> 1;   // 0..3
    const int warpN = warp & 1;    // 0..1
    const int mbase = warpM * 32;
    const int nbase = warpN * 32;

    const int bn = blockIdx.x;     // 0..124
    const int bm = blockIdx.y;     // 0..63

    float acc[2][4][4];
    #pragma unroll
    for (int mi = 0; mi < 2; ++mi)
        #pragma unroll
        for (int ni = 0; ni < 4; ++ni)
            #pragma unroll
            for (int c = 0; c < 4; ++c) acc[mi][ni][c] = 0.f;

    const float* Abase = g_Y + (size_t)(bm * BM) * K_OUT;          // row-major 8192x256
    const float* Bbase = W_out + (size_t)(bn * BN) * K_OUT;        // row-major 8000x256

    for (int kc = 0; kc < K_OUT; kc += BK) {
        // ---- stage A tile: 128 x 32 (4096 floats, 1024 float4, 4 per thread)
        {
            const float4* Ag = reinterpret_cast<const float4*>(Abase + kc);
            const int k4 = tid & 7;
            #pragma unroll
            for (int i = 0; i < 4; ++i) {
                const int m = (tid >> 3) + i * 32;
                float4 v = Ag[(size_t)m * (K_OUT / 4) + k4];
                uint4 u;
                u.x = f2tf32(v.x); u.y = f2tf32(v.y);
                u.z = f2tf32(v.z); u.w = f2tf32(v.w);
                *reinterpret_cast<uint4*>(&As[m * PAD_STRIDE + k4 * 4]) = u;
            }
        }
        // ---- stage B tile: 64 x 32 (2048 floats, 512 float4, 2 per thread)
        {
            const float4* Bg = reinterpret_cast<const float4*>(Bbase + kc);
            const int k4 = tid & 7;
            #pragma unroll
            for (int i = 0; i < 2; ++i) {
                const int n = (tid >> 3) + i * 32;
                float4 v = Bg[(size_t)n * (K_OUT / 4) + k4];
                uint4 u;
                u.x = f2tf32(v.x); u.y = f2tf32(v.y);
                u.z = f2tf32(v.z); u.w = f2tf32(v.w);
                *reinterpret_cast<uint4*>(&Bs[n * PAD_STRIDE + k4 * 4]) = u;
            }
        }
        __syncthreads();

        #pragma unroll
        for (int ks = 0; ks < BK; ks += 8) {
            unsigned a[2][4];
            #pragma unroll
            for (int mi = 0; mi < 2; ++mi) {
                const int r0 = (mbase + mi * 16 + g) * PAD_STRIDE + ks + t;
                a[mi][0] = As[r0];
                a[mi][1] = As[r0 + 8 * PAD_STRIDE];
                a[mi][2] = As[r0 + 4];
                a[mi][3] = As[r0 + 8 * PAD_STRIDE + 4];
            }
            unsigned bf[4][2];
            #pragma unroll
            for (int ni = 0; ni < 4; ++ni) {
                const int r = (nbase + ni * 8 + g) * PAD_STRIDE + ks + t;
                bf[ni][0] = Bs[r];
                bf[ni][1] = Bs[r + 4];
            }
            #pragma unroll
            for (int mi = 0; mi < 2; ++mi)
                #pragma unroll
                for (int ni = 0; ni < 4; ++ni)
                    mma_tf32(acc[mi][ni][0], acc[mi][ni][1],
                             acc[mi][ni][2], acc[mi][ni][3],
                             a[mi][0], a[mi][1], a[mi][2], a[mi][3],
                             bf[ni][0], bf[ni][1]);
        }
        __syncthreads();
    }

    // ---- epilogue: add bias, store (float2, cols 2t/2t+1 contiguous)
    #pragma unroll
    for (int ni = 0; ni < 4; ++ni) {
        const int col = bn * BN + nbase + ni * 8 + 2 * t;
        const float2 bv = *reinterpret_cast<const float2*>(&b_out[col]);
        #pragma unroll
        for (int mi = 0; mi < 2; ++mi) {
            const int row0 = bm * BM + mbase + mi * 16 + g;
            float2 v0; v0.x = acc[mi][ni][0] + bv.x; v0.y = acc[mi][ni][1] + bv.y;
            float2 v1; v1.x = acc[mi][ni][2] + bv.x; v1.y = acc[mi][ni][3] + bv.y;
            *reinterpret_cast<float2*>(&out[(size_t)row0 * N_OUT + col]) = v0;
            *reinterpret_cast<float2*>(&out[(size_t)(row0 + 8) * N_OUT + col]) = v1;
        }
    }
}

// ---------------------------------------------------------------------------
extern "C" void kernel_launch(void* const* d_in, const int* in_sizes, int n_in,
                              void* d_out, int out_size)
{
    const int*   X     = (const int*)  d_in[0];
    const float* h0    = (const float*)d_in[1];
    const float* W_ih  = (const float*)d_in[2];
    const float* b_ih  = (const float*)d_in[3];
    const float* W_hh  = (const float*)d_in[4];
    const float* b_hh  = (const float*)d_in[5];
    const float* W_out = (const float*)d_in[6];
    const float* b_out = (const float*)d_in[7];

    float* out = (float*)d_out;
    // out is (8192, 8000); h_last (1, 32, 256) follows if the harness
    // concatenates both return values.
    float* hlast = (out_size >= M_OUT * N_OUT + BATCH * HIDDEN)
                       ? out + (size_t)M_OUT * N_OUT
                       : nullptr;

    rnn_recurrence<<<BATCH, HIDDEN>>>(X, h0, W_ih, b_ih, W_hh, b_hh, hlast);

    dim3 grid(N_OUT / BN, M_OUT / BM);  // 125 x 64
    out_gemm<<<grid, 256>>>(W_out, b_out, out);
}

// round 7
// speedup vs baseline: 2.4669x; 2.4669x over previous
#include <cuda_runtime.h>
#include <cuda_bf16.h>
#include <cooperative_groups.h>
#include <cstdint>

namespace cg = cooperative_groups;

#define VOCAB  8000
#define HIDDEN 256
#define BATCH  32
#define SEQ    256
#define M_OUT  (SEQ*BATCH)      // 8192
#define N_OUT  VOCAB            // 8000
#define K_OUT  HIDDEN           // 256

// Scratch: Y (seq, batch, hidden) = hidden states for all steps (8 MB).
__device__ float g_Y[SEQ * BATCH * HIDDEN];

// ---------------------------------------------------------------------------
// Kernel 1: recurrence, register-resident W_hh.
// One batch element per 2-CTA cluster (64 CTAs total). Each CTA computes 128
// of the 256 outputs; 512 threads = 4 threads per output x 64 k-values each,
// so every thread holds its 64 W_hh weights in registers for the whole
// sequence (zero W traffic in the loop -> FFMA-bound, not L1-wavefront-bound).
// h is exchanged between the two CTAs via DSMEM + cluster.sync each step.
// fp32 throughout (recurrence precision).
// ---------------------------------------------------------------------------
__global__ __launch_bounds__(512, 1) __cluster_dims__(2, 1, 1)
void rnn_recurrence(const int* __restrict__ X,
                    const float* __restrict__ h0,
                    const float* __restrict__ W_ih,
                    const float* __restrict__ b_ih,
                    const float* __restrict__ W_hh,
                    const float* __restrict__ b_hh,
                    float* __restrict__ hlast)   // may be null
{
    cg::cluster_group cluster = cg::this_cluster();
    const unsigned rank = cluster.block_rank();      // 0 or 1
    const int b = blockIdx.x >> 1;                   // batch element

    __shared__ float h[2][HIDDEN];                   // double-buffered full h

    const int tid = threadIdx.x;
    const int jl  = tid >> 2;                        // local output 0..127
    const int s   = tid & 3;                         // k-slice 0..3
    const int j   = (int)rank * 128 + jl;            // global output row

    // Cache this thread's 64 W_hh weights (row j, cols s*64..s*64+63).
    float4 Wreg[16];
    {
        const float4* wp = reinterpret_cast<const float4*>(
            W_hh + (size_t)j * HIDDEN + s * 64);
        #pragma unroll
        for (int i = 0; i < 16; ++i) Wreg[i] = wp[i];
    }

    // init h buffer 0 with h0 (both CTAs load the full vector)
    if (tid < HIDDEN) h[0][tid] = h0[b * HIDDEN + tid];

    float bias = 0.f;
    if (s == 0) bias = b_ih[j] + b_hh[j];
    const float* __restrict__ wih_row = W_ih + (size_t)j * VOCAB;
    const int*   __restrict__ xrow    = X + b * SEQ;

    // Peer CTA's h buffer (DSMEM).
    float* h_peer = cluster.map_shared_rank(&h[0][0], rank ^ 1);

    cluster.sync();

    int p = 0;
    int idx = xrow[0];
    for (int t = 0; t < SEQ; ++t) {
        // issue the embedding gather early (only the s==0 lane uses it)
        float xg = 0.f;
        if (s == 0) xg = wih_row[idx];

        // partial dot: W_hh[j, s*64 .. s*64+63] . h[s*64 ..]
        const float4* hv = reinterpret_cast<const float4*>(&h[p][s * 64]);
        float a0 = 0.f, a1 = 0.f, a2 = 0.f, a3 = 0.f;
        #pragma unroll
        for (int i = 0; i < 16; ++i) {
            const float4 hh = hv[i];            // smem broadcast (N=1)
            a0 = fmaf(Wreg[i].x, hh.x, a0);
            a1 = fmaf(Wreg[i].y, hh.y, a1);
            a2 = fmaf(Wreg[i].z, hh.z, a2);
            a3 = fmaf(Wreg[i].w, hh.w, a3);
        }
        float acc = (a0 + a1) + (a2 + a3);
        // quad reduction (the 4 slices of one output are consecutive lanes)
        acc += __shfl_down_sync(0xffffffffu, acc, 2);
        acc += __shfl_down_sync(0xffffffffu, acc, 1);

        if (t + 1 < SEQ) idx = xrow[t + 1];     // prefetch next gather index

        if (s == 0) {
            const float hn = tanhf(xg + bias + acc);
            h[p ^ 1][j] = hn;                              // local copy
            h_peer[(p ^ 1) * HIDDEN + j] = hn;             // peer copy (DSMEM)
            g_Y[((size_t)t * BATCH + b) * HIDDEN + j] = hn;
        }
        cluster.sync();   // orders DSMEM writes before next step's reads
        p ^= 1;
    }
    if (s == 0 && hlast) hlast[b * HIDDEN + j] = h[p][j];
}

// ---------------------------------------------------------------------------
// Kernel 2: out = Y @ W_out^T + b_out via tf32 mma.sync (m16n8k8).
// Block tile 128(M) x 64(N), BK=32.  8 warps: 4(M) x 2(N), warp tile 32x32.
// Smem padded to stride 36 words -> conflict-free fragment loads.
// ---------------------------------------------------------------------------
__device__ __forceinline__ unsigned f2tf32(float x) {
    unsigned r;
    asm("cvt.rna.tf32.f32 %0, %1;" : "=r"(r) : "f"(x));
    return r;
}

__device__ __forceinline__ void mma_tf32(float& d0, float& d1, float& d2, float& d3,
                                         unsigned a0, unsigned a1, unsigned a2, unsigned a3,
                                         unsigned b0, unsigned b1)
{
    asm volatile(
        "mma.sync.aligned.m16n8k8.row.col.f32.tf32.tf32.f32 "
        "{%0,%1,%2,%3}, {%4,%5,%6,%7}, {%8,%9}, {%0,%1,%2,%3};\n"
        : "+f"(d0), "+f"(d1), "+f"(d2), "+f"(d3)
        : "r"(a0), "r"(a1), "r"(a2), "r"(a3), "r"(b0), "r"(b1));
}

#define BM 128
#define BN 64
#define BK 32
#define PAD_STRIDE 36   // BK + 4 words

__global__ __launch_bounds__(256, 2)
void out_gemm(const float* __restrict__ W_out,
              const float* __restrict__ b_out,
              float* __restrict__ out)
{
    __shared__ unsigned As[BM * PAD_STRIDE];  // tf32 bits
    __shared__ unsigned Bs[BN * PAD_STRIDE];

    const int tid  = threadIdx.x;
    const int lane = tid & 31;
    const int warp = tid >> 5;
    const int g = lane >> 2;       // group id 0..7
    const int t = lane & 3;        // thread-in-group 0..3
    const int warpM = warp >> 1;   // 0..3
    const int warpN = warp & 1;    // 0..1
    const int mbase = warpM * 32;
    const int nbase = warpN * 32;

    const int bn = blockIdx.x;     // 0..124
    const int bm = blockIdx.y;     // 0..63

    float acc[2][4][4];
    #pragma unroll
    for (int mi = 0; mi < 2; ++mi)
        #pragma unroll
        for (int ni = 0; ni < 4; ++ni)
            #pragma unroll
            for (int c = 0; c < 4; ++c) acc[mi][ni][c] = 0.f;

    const float* Abase = g_Y + (size_t)(bm * BM) * K_OUT;          // row-major 8192x256
    const float* Bbase = W_out + (size_t)(bn * BN) * K_OUT;        // row-major 8000x256

    for (int kc = 0; kc < K_OUT; kc += BK) {
        // ---- stage A tile: 128 x 32 (4096 floats, 1024 float4, 4 per thread)
        {
            const float4* Ag = reinterpret_cast<const float4*>(Abase + kc);
            const int k4 = tid & 7;
            #pragma unroll
            for (int i = 0; i < 4; ++i) {
                const int m = (tid >> 3) + i * 32;
                float4 v = Ag[(size_t)m * (K_OUT / 4) + k4];
                uint4 u;
                u.x = f2tf32(v.x); u.y = f2tf32(v.y);
                u.z = f2tf32(v.z); u.w = f2tf32(v.w);
                *reinterpret_cast<uint4*>(&As[m * PAD_STRIDE + k4 * 4]) = u;
            }
        }
        // ---- stage B tile: 64 x 32 (2048 floats, 512 float4, 2 per thread)
        {
            const float4* Bg = reinterpret_cast<const float4*>(Bbase + kc);
            const int k4 = tid & 7;
            #pragma unroll
            for (int i = 0; i < 2; ++i) {
                const int n = (tid >> 3) + i * 32;
                float4 v = Bg[(size_t)n * (K_OUT / 4) + k4];
                uint4 u;
                u.x = f2tf32(v.x); u.y = f2tf32(v.y);
                u.z = f2tf32(v.z); u.w = f2tf32(v.w);
                *reinterpret_cast<uint4*>(&Bs[n * PAD_STRIDE + k4 * 4]) = u;
            }
        }
        __syncthreads();

        #pragma unroll
        for (int ks = 0; ks < BK; ks += 8) {
            unsigned a[2][4];
            #pragma unroll
            for (int mi = 0; mi < 2; ++mi) {
                const int r0 = (mbase + mi * 16 + g) * PAD_STRIDE + ks + t;
                a[mi][0] = As[r0];
                a[mi][1] = As[r0 + 8 * PAD_STRIDE];
                a[mi][2] = As[r0 + 4];
                a[mi][3] = As[r0 + 8 * PAD_STRIDE + 4];
            }
            unsigned bf[4][2];
            #pragma unroll
            for (int ni = 0; ni < 4; ++ni) {
                const int r = (nbase + ni * 8 + g) * PAD_STRIDE + ks + t;
                bf[ni][0] = Bs[r];
                bf[ni][1] = Bs[r + 4];
            }
            #pragma unroll
            for (int mi = 0; mi < 2; ++mi)
                #pragma unroll
                for (int ni = 0; ni < 4; ++ni)
                    mma_tf32(acc[mi][ni][0], acc[mi][ni][1],
                             acc[mi][ni][2], acc[mi][ni][3],
                             a[mi][0], a[mi][1], a[mi][2], a[mi][3],
                             bf[ni][0], bf[ni][1]);
        }
        __syncthreads();
    }

    // ---- epilogue: add bias, store (float2, cols 2t/2t+1 contiguous)
    #pragma unroll
    for (int ni = 0; ni < 4; ++ni) {
        const int col = bn * BN + nbase + ni * 8 + 2 * t;
        const float2 bv = *reinterpret_cast<const float2*>(&b_out[col]);
        #pragma unroll
        for (int mi = 0; mi < 2; ++mi) {
            const int row0 = bm * BM + mbase + mi * 16 + g;
            float2 v0; v0.x = acc[mi][ni][0] + bv.x; v0.y = acc[mi][ni][1] + bv.y;
            float2 v1; v1.x = acc[mi][ni][2] + bv.x; v1.y = acc[mi][ni][3] + bv.y;
            *reinterpret_cast<float2*>(&out[(size_t)row0 * N_OUT + col]) = v0;
            *reinterpret_cast<float2*>(&out[(size_t)(row0 + 8) * N_OUT + col]) = v1;
        }
    }
}

// ---------------------------------------------------------------------------
extern "C" void kernel_launch(void* const* d_in, const int* in_sizes, int n_in,
                              void* d_out, int out_size)
{
    const int*   X     = (const int*)  d_in[0];
    const float* h0    = (const float*)d_in[1];
    const float* W_ih  = (const float*)d_in[2];
    const float* b_ih  = (const float*)d_in[3];
    const float* W_hh  = (const float*)d_in[4];
    const float* b_hh  = (const float*)d_in[5];
    const float* W_out = (const float*)d_in[6];
    const float* b_out = (const float*)d_in[7];

    float* out = (float*)d_out;
    // out is (8192, 8000); h_last (1, 32, 256) follows if the harness
    // concatenates both return values.
    float* hlast = (out_size >= M_OUT * N_OUT + BATCH * HIDDEN)
                       ? out + (size_t)M_OUT * N_OUT
                       : nullptr;

    // 64 CTAs = 32 clusters of 2 (cluster dims are a compile-time kernel attr)
    rnn_recurrence<<<2 * BATCH, 512>>>(X, h0, W_ih, b_ih, W_hh, b_hh, hlast);

    dim3 grid(N_OUT / BN, M_OUT / BM);  // 125 x 64
    out_gemm<<<grid, 256>>>(W_out, b_out, out);
}

// round 9
// speedup vs baseline: 4.0598x; 1.6457x over previous
#include <cuda_runtime.h>
#include <cuda_fp16.h>
#include <cuda_bf16.h>
#include <cstdint>

#define VOCAB  8000
#define HIDDEN 256
#define BATCH  32
#define SEQ    256
#define M_OUT  (SEQ*BATCH)      // 8192
#define N_OUT  VOCAB            // 8000
#define K_OUT  HIDDEN           // 256

// Scratch: Y (seq, batch, hidden) = hidden states for all steps (8 MB).
__device__ float g_Y[SEQ * BATCH * HIDDEN];

// ---------------------------------------------------------------------------
// Kernel 1: recurrence. ONE CTA per batch element, W_hh cached in SHARED
// MEMORY as fp16 (135 KB < 228 KB carveout; fp32 would be 256 KB and not fit).
// No cross-CTA communication: per-step sync is a plain __syncthreads (~7 cyc)
// instead of cluster.sync (~490 cyc + CCTL.IVALL L1 flush) — that was the
// R7 bottleneck. fp16 weights add ~1.4e-4 rel err through a contracting
// recurrence -> ~3.4e-4 in Y, under the 1e-3 gate. Accumulation is fp32.
//
// Thread map: 512 threads = 16 warps. warp w: k-slice s = w>>3 (0/1),
// output j = (w&7)*32 + lane. W smem row stride = 264 halves = 33 quads
// (odd) -> LDS.128 per phase hits 8 distinct bank-quads: conflict-free.
// h reads are warp-uniform broadcasts. The two k-slices combine through a
// smem partial array (partner thread lives in a different warp).
// ---------------------------------------------------------------------------
#define WROW 264                       // halves per W row (16B aligned, 33 quads)
#define SM_W_BYTES (HIDDEN * WROW * 2) // 135168
#define SM_H_OFF   SM_W_BYTES
#define SM_P_OFF   (SM_H_OFF + 2 * HIDDEN * 4)
#define SM_TOTAL   (SM_P_OFF + HIDDEN * 4)   // 138240 B

__global__ __launch_bounds__(512, 1)
void rnn_recurrence(const int* __restrict__ X,
                    const float* __restrict__ h0,
                    const float* __restrict__ W_ih,
                    const float* __restrict__ b_ih,
                    const float* __restrict__ W_hh,
                    const float* __restrict__ b_hh,
                    float* __restrict__ hlast)   // may be null
{
    extern __shared__ char dyn[];
    __half* Wsm  = reinterpret_cast<__half*>(dyn);
    float*  hbuf = reinterpret_cast<float*>(dyn + SM_H_OFF);  // [2][256]
    float*  part = reinterpret_cast<float*>(dyn + SM_P_OFF);  // [256]

    const int tid = threadIdx.x;
    const int b   = blockIdx.x;

    // One-time: convert W_hh (fp32, global/L2) -> fp16 smem, padded rows.
    for (int e = tid; e < HIDDEN * HIDDEN; e += 512) {
        const int j = e >> 8, k = e & 255;
        Wsm[j * WROW + k] = __float2half(W_hh[e]);
    }
    if (tid < HIDDEN) hbuf[tid] = h0[b * HIDDEN + tid];   // buffer 0

    const int w    = tid >> 5;
    const int lane = tid & 31;
    const int s    = w >> 3;                 // k-slice 0/1
    const int j    = ((w & 7) << 5) + lane;  // output row 0..255

    float bias = 0.f;
    if (s == 0) bias = b_ih[j] + b_hh[j];
    const float* __restrict__ wih_row = W_ih + (size_t)j * VOCAB;
    const int*   __restrict__ xrow    = X + b * SEQ;
    __syncthreads();

    const uint4* __restrict__ wvec =
        reinterpret_cast<const uint4*>(Wsm + j * WROW + s * 128);  // 16 quads

    int p = 0;
    int idx = xrow[0];
    for (int t = 0; t < SEQ; ++t) {
        // issue the embedding gather early (only s==0 consumes it, at tanh)
        float xg = 0.f;
        if (s == 0) xg = __ldg(wih_row + idx);

        const float4* hv =
            reinterpret_cast<const float4*>(hbuf + p * HIDDEN + s * 128);
        float a0 = 0.f, a1 = 0.f, a2 = 0.f, a3 = 0.f;
        #pragma unroll
        for (int i = 0; i < 16; ++i) {
            const uint4  wq  = wvec[i];          // 8 fp16 weights
            const float4 hA  = hv[2 * i];        // broadcast
            const float4 hB  = hv[2 * i + 1];
            const float2 w01 = __half22float2(*reinterpret_cast<const __half2*>(&wq.x));
            const float2 w23 = __half22float2(*reinterpret_cast<const __half2*>(&wq.y));
            const float2 w45 = __half22float2(*reinterpret_cast<const __half2*>(&wq.z));
            const float2 w67 = __half22float2(*reinterpret_cast<const __half2*>(&wq.w));
            a0 = fmaf(w01.x, hA.x, a0); a1 = fmaf(w01.y, hA.y, a1);
            a2 = fmaf(w23.x, hA.z, a2); a3 = fmaf(w23.y, hA.w, a3);
            a0 = fmaf(w45.x, hB.x, a0); a1 = fmaf(w45.y, hB.y, a1);
            a2 = fmaf(w67.x, hB.z, a2); a3 = fmaf(w67.y, hB.w, a3);
        }
        float acc = (a0 + a1) + (a2 + a3);
        if (t + 1 < SEQ) idx = xrow[t + 1];

        if (s == 1) part[j] = acc;
        __syncthreads();
        if (s == 0) {
            const float hn = tanhf(xg + bias + acc + part[j]);
            hbuf[(p ^ 1) * HIDDEN + j] = hn;
            g_Y[((size_t)t * BATCH + b) * HIDDEN + j] = hn;
        }
        __syncthreads();
        p ^= 1;
    }
    if (s == 0 && hlast) hlast[b * HIDDEN + j] = hbuf[p * HIDDEN + j];
}

// ---------------------------------------------------------------------------
// Kernel 2: out = Y @ W_out^T + b_out via tf32 mma.sync (m16n8k8).
// Block tile 128(M) x 64(N), BK=32.  8 warps: 4(M) x 2(N), warp tile 32x32.
// Smem padded to stride 36 words -> conflict-free fragment loads.
// Register-prefetch software pipeline — next tile's LDGs issue right
// after the barrier so global latency overlaps the MMA section.
// ---------------------------------------------------------------------------
__device__ __forceinline__ unsigned f2tf32(float x) {
    unsigned r;
    asm("cvt.rna.tf32.f32 %0, %1;" : "=r"(r) : "f"(x));
    return r;
}

__device__ __forceinline__ void mma_tf32(float& d0, float& d1, float& d2, float& d3,
                                         unsigned a0, unsigned a1, unsigned a2, unsigned a3,
                                         unsigned b0, unsigned b1)
{
    asm volatile(
        "mma.sync.aligned.m16n8k8.row.col.f32.tf32.tf32.f32 "
        "{%0,%1,%2,%3}, {%4,%5,%6,%7}, {%8,%9}, {%0,%1,%2,%3};\n"
        : "+f"(d0), "+f"(d1), "+f"(d2), "+f"(d3)
        : "r"(a0), "r"(a1), "r"(a2), "r"(a3), "r"(b0), "r"(b1));
}

#define BM 128
#define BN 64
#define BK 32
#define PAD_STRIDE 36   // BK + 4 words

__global__ __launch_bounds__(256, 2)
void out_gemm(const float* __restrict__ W_out,
              const float* __restrict__ b_out,
              float* __restrict__ out)
{
    __shared__ unsigned As[BM * PAD_STRIDE];  // tf32 bits
    __shared__ unsigned Bs[BN * PAD_STRIDE];

    const int tid  = threadIdx.x;
    const int lane = tid & 31;
    const int warp = tid >> 5;
    const int g = lane >> 2;       // group id 0..7
    const int t = lane & 3;        // thread-in-group 0..3
    const int warpM = warp >> 1;   // 0..3
    const int warpN = warp & 1;    // 0..1
    const int mbase = warpM * 32;
    const int nbase = warpN * 32;

    const int bn = blockIdx.x;     // 0..124
    const int bm = blockIdx.y;     // 0..63

    float acc[2][4][4];
    #pragma unroll
    for (int mi = 0; mi < 2; ++mi)
        #pragma unroll
        for (int ni = 0; ni < 4; ++ni)
            #pragma unroll
            for (int c = 0; c < 4; ++c) acc[mi][ni][c] = 0.f;

    const float* Abase = g_Y + (size_t)(bm * BM) * K_OUT;          // row-major 8192x256
    const float* Bbase = W_out + (size_t)(bn * BN) * K_OUT;        // row-major 8000x256

    const int k4 = tid & 7;
    const int r8 = tid >> 3;

    // prologue: prefetch tile kc=0 into registers
    float4 ra[4];
    float4 rb[2];
    {
        const float4* Ag = reinterpret_cast<const float4*>(Abase);
        const float4* Bg = reinterpret_cast<const float4*>(Bbase);
        #pragma unroll
        for (int i = 0; i < 4; ++i)
            ra[i] = Ag[(size_t)(r8 + i * 32) * (K_OUT / 4) + k4];
        #pragma unroll
        for (int i = 0; i < 2; ++i)
            rb[i] = Bg[(size_t)(r8 + i * 32) * (K_OUT / 4) + k4];
    }

    for (int kc = 0; kc < K_OUT; kc += BK) {
        // ---- commit staged registers to smem (tf32 convert)
        #pragma unroll
        for (int i = 0; i < 4; ++i) {
            uint4 u;
            u.x = f2tf32(ra[i].x); u.y = f2tf32(ra[i].y);
            u.z = f2tf32(ra[i].z); u.w = f2tf32(ra[i].w);
            *reinterpret_cast<uint4*>(&As[(r8 + i * 32) * PAD_STRIDE + k4 * 4]) = u;
        }
        #pragma unroll
        for (int i = 0; i < 2; ++i) {
            uint4 u;
            u.x = f2tf32(rb[i].x); u.y = f2tf32(rb[i].y);
            u.z = f2tf32(rb[i].z); u.w = f2tf32(rb[i].w);
            *reinterpret_cast<uint4*>(&Bs[(r8 + i * 32) * PAD_STRIDE + k4 * 4]) = u;
        }
        __syncthreads();

        // ---- prefetch NEXT tile (LDGs overlap the MMA section below)
        if (kc + BK < K_OUT) {
            const float4* Ag = reinterpret_cast<const float4*>(Abase + kc + BK);
            const float4* Bg = reinterpret_cast<const float4*>(Bbase + kc + BK);
            #pragma unroll
            for (int i = 0; i < 4; ++i)
                ra[i] = Ag[(size_t)(r8 + i * 32) * (K_OUT / 4) + k4];
            #pragma unroll
            for (int i = 0; i < 2; ++i)
                rb[i] = Bg[(size_t)(r8 + i * 32) * (K_OUT / 4) + k4];
        }

        #pragma unroll
        for (int ks = 0; ks < BK; ks += 8) {
            unsigned a[2][4];
            #pragma unroll
            for (int mi = 0; mi < 2; ++mi) {
                const int r0 = (mbase + mi * 16 + g) * PAD_STRIDE + ks + t;
                a[mi][0] = As[r0];
                a[mi][1] = As[r0 + 8 * PAD_STRIDE];
                a[mi][2] = As[r0 + 4];
                a[mi][3] = As[r0 + 8 * PAD_STRIDE + 4];
            }
            unsigned bf[4][2];
            #pragma unroll
            for (int ni = 0; ni < 4; ++ni) {
                const int r = (nbase + ni * 8 + g) * PAD_STRIDE + ks + t;
                bf[ni][0] = Bs[r];
                bf[ni][1] = Bs[r + 4];
            }
            #pragma unroll
            for (int mi = 0; mi < 2; ++mi)
                #pragma unroll
                for (int ni = 0; ni < 4; ++ni)
                    mma_tf32(acc[mi][ni][0], acc[mi][ni][1],
                             acc[mi][ni][2], acc[mi][ni][3],
                             a[mi][0], a[mi][1], a[mi][2], a[mi][3],
                             bf[ni][0], bf[ni][1]);
        }
        __syncthreads();
    }

    // ---- epilogue: add bias, store (float2, cols 2t/2t+1 contiguous)
    #pragma unroll
    for (int ni = 0; ni < 4; ++ni) {
        const int col = bn * BN + nbase + ni * 8 + 2 * t;
        const float2 bv = *reinterpret_cast<const float2*>(&b_out[col]);
        #pragma unroll
        for (int mi = 0; mi < 2; ++mi) {
            const int row0 = bm * BM + mbase + mi * 16 + g;
            float2 v0; v0.x = acc[mi][ni][0] + bv.x; v0.y = acc[mi][ni][1] + bv.y;
            float2 v1; v1.x = acc[mi][ni][2] + bv.x; v1.y = acc[mi][ni][3] + bv.y;
            *reinterpret_cast<float2*>(&out[(size_t)row0 * N_OUT + col]) = v0;
            *reinterpret_cast<float2*>(&out[(size_t)(row0 + 8) * N_OUT + col]) = v1;
        }
    }
}

// ---------------------------------------------------------------------------
extern "C" void kernel_launch(void* const* d_in, const int* in_sizes, int n_in,
                              void* d_out, int out_size)
{
    const int*   X     = (const int*)  d_in[0];
    const float* h0    = (const float*)d_in[1];
    const float* W_ih  = (const float*)d_in[2];
    const float* b_ih  = (const float*)d_in[3];
    const float* W_hh  = (const float*)d_in[4];
    const float* b_hh  = (const float*)d_in[5];
    const float* W_out = (const float*)d_in[6];
    const float* b_out = (const float*)d_in[7];

    float* out = (float*)d_out;
    float* hlast = (out_size >= M_OUT * N_OUT + BATCH * HIDDEN)
                       ? out + (size_t)M_OUT * N_OUT
                       : nullptr;

    // >48KB dynamic smem needs the attribute. Called unconditionally every
    // launch (idempotent, non-stream, capture-safe) — no static guards.
    cudaFuncSetAttribute(rnn_recurrence,
                         cudaFuncAttributeMaxDynamicSharedMemorySize, SM_TOTAL);

    rnn_recurrence<<<BATCH, 512, SM_TOTAL>>>(X, h0, W_ih, b_ih, W_hh, b_hh, hlast);

    dim3 grid(N_OUT / BN, M_OUT / BM);  // 125 x 64
    out_gemm<<<grid, 256>>>(W_out, b_out, out);
}

// round 10
// speedup vs baseline: 4.3740x; 1.0774x over previous
#include <cuda_runtime.h>
#include <cuda_fp16.h>
#include <cuda_bf16.h>
#include <cstdint>

#define VOCAB  8000
#define HIDDEN 256
#define BATCH  32
#define SEQ    256
#define M_OUT  (SEQ*BATCH)      // 8192
#define N_OUT  VOCAB            // 8000
#define K_OUT  HIDDEN           // 256

// Scratch: Y (seq, batch, hidden) hidden states, stored fp16 for the GEMM (4 MB).
__device__ __half g_Yh[(size_t)SEQ * BATCH * HIDDEN];

// ---------------------------------------------------------------------------
// Kernel 1: recurrence. ONE CTA per batch element, W_hh cached in smem fp16.
// R10: 1024 threads (32 warps = 8/SMSP, vs 4 before) — same instruction
// total, 2x the latency hiding; R9 measured only ~53% issue efficiency.
// 4 k-slices x 64 k-values per thread; fp32 h and fp32 accumulation
// (recurrence state precision preserved; only g_Yh is rounded to fp16).
// ---------------------------------------------------------------------------
#define WROW 264                       // halves per W row (16B aligned, 33 quads)
#define SM_W_BYTES (HIDDEN * WROW * 2) // 135168
#define SM_H_OFF   SM_W_BYTES
#define SM_P_OFF   (SM_H_OFF + 2 * HIDDEN * 4)
#define SM_TOTAL   (SM_P_OFF + 3 * HIDDEN * 4)   // 140288 B

__global__ __launch_bounds__(1024, 1)
void rnn_recurrence(const int* __restrict__ X,
                    const float* __restrict__ h0,
                    const float* __restrict__ W_ih,
                    const float* __restrict__ b_ih,
                    const float* __restrict__ W_hh,
                    const float* __restrict__ b_hh,
                    float* __restrict__ hlast)   // may be null
{
    extern __shared__ char dyn[];
    __half* Wsm  = reinterpret_cast<__half*>(dyn);
    float*  hbuf = reinterpret_cast<float*>(dyn + SM_H_OFF);  // [2][256]
    float*  part = reinterpret_cast<float*>(dyn + SM_P_OFF);  // [3][256]

    const int tid = threadIdx.x;
    const int b   = blockIdx.x;

    // One-time: convert W_hh (fp32) -> fp16 smem, padded rows.
    for (int e = tid; e < HIDDEN * HIDDEN; e += 1024) {
        const int j = e >> 8, k = e & 255;
        Wsm[j * WROW + k] = __float2half(W_hh[e]);
    }
    if (tid < HIDDEN) hbuf[tid] = h0[b * HIDDEN + tid];   // buffer 0

    const int w    = tid >> 5;
    const int lane = tid & 31;
    const int s    = w >> 3;                 // k-slice 0..3 (64 k each)
    const int j    = ((w & 7) << 5) + lane;  // output row 0..255

    float bias = 0.f;
    if (s == 0) bias = b_ih[j] + b_hh[j];
    const float* __restrict__ wih_row = W_ih + (size_t)j * VOCAB;
    const int*   __restrict__ xrow    = X + b * SEQ;
    __syncthreads();

    const uint4* __restrict__ wvec =
        reinterpret_cast<const uint4*>(Wsm + j * WROW + s * 64);  // 8 quads

    int p = 0;
    int idx = xrow[0];
    for (int t = 0; t < SEQ; ++t) {
        float xg = 0.f;
        if (s == 0) xg = __ldg(wih_row + idx);   // gather, consumed at tanh

        const float4* hv =
            reinterpret_cast<const float4*>(hbuf + p * HIDDEN + s * 64);
        float a0 = 0.f, a1 = 0.f, a2 = 0.f, a3 = 0.f;
        #pragma unroll
        for (int i = 0; i < 8; ++i) {
            const uint4  wq  = wvec[i];          // 8 fp16 weights
            const float4 hA  = hv[2 * i];        // broadcast (warp-uniform)
            const float4 hB  = hv[2 * i + 1];
            const float2 w01 = __half22float2(*reinterpret_cast<const __half2*>(&wq.x));
            const float2 w23 = __half22float2(*reinterpret_cast<const __half2*>(&wq.y));
            const float2 w45 = __half22float2(*reinterpret_cast<const __half2*>(&wq.z));
            const float2 w67 = __half22float2(*reinterpret_cast<const __half2*>(&wq.w));
            a0 = fmaf(w01.x, hA.x, a0); a1 = fmaf(w01.y, hA.y, a1);
            a2 = fmaf(w23.x, hA.z, a2); a3 = fmaf(w23.y, hA.w, a3);
            a0 = fmaf(w45.x, hB.x, a0); a1 = fmaf(w45.y, hB.y, a1);
            a2 = fmaf(w67.x, hB.z, a2); a3 = fmaf(w67.y, hB.w, a3);
        }
        float acc = (a0 + a1) + (a2 + a3);
        if (t + 1 < SEQ) idx = xrow[t + 1];

        if (s) part[((s - 1) << 8) + j] = acc;
        __syncthreads();
        if (s == 0) {
            const float hn = tanhf(xg + bias + acc +
                                   part[j] + part[256 + j] + part[512 + j]);
            hbuf[(p ^ 1) * HIDDEN + j] = hn;
            g_Yh[((size_t)t * BATCH + b) * HIDDEN + j] = __float2half(hn);
        }
        __syncthreads();
        p ^= 1;
    }
    if (s == 0 && hlast) hlast[b * HIDDEN + j] = hbuf[p * HIDDEN + j];
}

// ---------------------------------------------------------------------------
// Kernel 2: out = Y @ W_out^T + b_out via fp16 mma.sync m16n8k16, fp32 accum.
// R10: fp16 (from tf32 k8) halves fragment LDS, MMA count, and smem bytes —
// R9 showed L1 (smem) at 77% was the cap. Block 128x64, BK=32.
// Smem layout: half2 rows, stride 20 half2 (16+4 pad) -> fragment access
// pattern g*20+t and g*20+t+4 are bijective mod 32: conflict-free.
// Register double-buffer on global loads retained. 3 CTAs/SM (15.4 KB smem).
// ---------------------------------------------------------------------------
__device__ __forceinline__ void mma_f16(float& d0, float& d1, float& d2, float& d3,
                                        unsigned a0, unsigned a1, unsigned a2, unsigned a3,
                                        unsigned b0, unsigned b1)
{
    asm volatile(
        "mma.sync.aligned.m16n8k16.row.col.f32.f16.f16.f32 "
        "{%0,%1,%2,%3}, {%4,%5,%6,%7}, {%8,%9}, {%0,%1,%2,%3};\n"
        : "+f"(d0), "+f"(d1), "+f"(d2), "+f"(d3)
        : "r"(a0), "r"(a1), "r"(a2), "r"(a3), "r"(b0), "r"(b1));
}

#define BM 128
#define BN 64
#define BK 32          // k elements per stage
#define S2 20          // row stride in half2 units (BK/2 + 4 pad)

__global__ __launch_bounds__(256, 3)
void out_gemm(const float* __restrict__ W_out,
              const float* __restrict__ b_out,
              float* __restrict__ out)
{
    __shared__ __half2 As[BM * S2];   // 10240 B
    __shared__ __half2 Bs[BN * S2];   //  5120 B

    const int tid  = threadIdx.x;
    const int lane = tid & 31;
    const int warp = tid >> 5;
    const int g = lane >> 2;       // group id 0..7
    const int t = lane & 3;        // thread-in-group 0..3
    const int warpM = warp >> 1;   // 0..3
    const int warpN = warp & 1;    // 0..1
    const int mbase = warpM * 32;
    const int nbase = warpN * 32;

    const int bn = blockIdx.x;     // 0..124
    const int bm = blockIdx.y;     // 0..63

    float acc[2][4][4];
    #pragma unroll
    for (int mi = 0; mi < 2; ++mi)
        #pragma unroll
        for (int ni = 0; ni < 4; ++ni)
            #pragma unroll
            for (int c = 0; c < 4; ++c) acc[mi][ni][c] = 0.f;

    const __half* Abase = g_Yh + (size_t)(bm * BM) * K_OUT;   // row-major 8192x256
    const float*  Bbase = W_out + (size_t)(bn * BN) * K_OUT;  // row-major 8000x256

    // staging maps
    const int aq = tid & 3;        // 4 uint4 (32 halves) per A row
    const int ar = tid >> 2;       // 0..63 -> rows ar, ar+64
    const int bc = tid & 7;        // 8 float4 per B row
    const int br = tid >> 3;       // 0..31 -> rows br, br+32

    // prologue: prefetch tile kc=0 into registers
    uint4  ra[2];
    float4 rb[2];
    {
        #pragma unroll
        for (int i = 0; i < 2; ++i)
            ra[i] = *reinterpret_cast<const uint4*>(
                Abase + (size_t)(ar + i * 64) * K_OUT + aq * 8);
        #pragma unroll
        for (int i = 0; i < 2; ++i)
            rb[i] = *reinterpret_cast<const float4*>(
                Bbase + (size_t)(br + i * 32) * K_OUT + bc * 4);
    }

    for (int kc = 0; kc < K_OUT; kc += BK) {
        // ---- commit staged registers to smem
        #pragma unroll
        for (int i = 0; i < 2; ++i)
            *reinterpret_cast<uint4*>(&As[(ar + i * 64) * S2 + aq * 4]) = ra[i];
        #pragma unroll
        for (int i = 0; i < 2; ++i) {
            __half2 h01 = __floats2half2_rn(rb[i].x, rb[i].y);
            __half2 h23 = __floats2half2_rn(rb[i].z, rb[i].w);
            uint2 u;
            u.x = *reinterpret_cast<unsigned*>(&h01);
            u.y = *reinterpret_cast<unsigned*>(&h23);
            *reinterpret_cast<uint2*>(&Bs[(br + i * 32) * S2 + bc * 2]) = u;
        }
        __syncthreads();

        // ---- prefetch NEXT tile (overlaps the MMA section)
        if (kc + BK < K_OUT) {
            #pragma unroll
            for (int i = 0; i < 2; ++i)
                ra[i] = *reinterpret_cast<const uint4*>(
                    Abase + (size_t)(ar + i * 64) * K_OUT + kc + BK + aq * 8);
            #pragma unroll
            for (int i = 0; i < 2; ++i)
                rb[i] = *reinterpret_cast<const float4*>(
                    Bbase + (size_t)(br + i * 32) * K_OUT + kc + BK + bc * 4);
        }

        // ---- 2 k16 steps per stage
        #pragma unroll
        for (int ko = 0; ko < BK / 2; ko += 8) {
            unsigned a[2][4];
            #pragma unroll
            for (int mi = 0; mi < 2; ++mi) {
                const int r0 = (mbase + mi * 16 + g) * S2 + ko + t;
                const int r1 = (mbase + mi * 16 + 8 + g) * S2 + ko + t;
                a[mi][0] = *reinterpret_cast<const unsigned*>(&As[r0]);
                a[mi][1] = *reinterpret_cast<const unsigned*>(&As[r1]);
                a[mi][2] = *reinterpret_cast<const unsigned*>(&As[r0 + 4]);
                a[mi][3] = *reinterpret_cast<const unsigned*>(&As[r1 + 4]);
            }
            unsigned bf[4][2];
            #pragma unroll
            for (int ni = 0; ni < 4; ++ni) {
                const int r = (nbase + ni * 8 + g) * S2 + ko + t;
                bf[ni][0] = *reinterpret_cast<const unsigned*>(&Bs[r]);
                bf[ni][1] = *reinterpret_cast<const unsigned*>(&Bs[r + 4]);
            }
            #pragma unroll
            for (int mi = 0; mi < 2; ++mi)
                #pragma unroll
                for (int ni = 0; ni < 4; ++ni)
                    mma_f16(acc[mi][ni][0], acc[mi][ni][1],
                            acc[mi][ni][2], acc[mi][ni][3],
                            a[mi][0], a[mi][1], a[mi][2], a[mi][3],
                            bf[ni][0], bf[ni][1]);
        }
        __syncthreads();
    }

    // ---- epilogue: add bias, store (float2, cols 2t/2t+1 contiguous)
    #pragma unroll
    for (int ni = 0; ni < 4; ++ni) {
        const int col = bn * BN + nbase + ni * 8 + 2 * t;
        const float2 bv = *reinterpret_cast<const float2*>(&b_out[col]);
        #pragma unroll
        for (int mi = 0; mi < 2; ++mi) {
            const int row0 = bm * BM + mbase + mi * 16 + g;
            float2 v0; v0.x = acc[mi][ni][0] + bv.x; v0.y = acc[mi][ni][1] + bv.y;
            float2 v1; v1.x = acc[mi][ni][2] + bv.x; v1.y = acc[mi][ni][3] + bv.y;
            *reinterpret_cast<float2*>(&out[(size_t)row0 * N_OUT + col]) = v0;
            *reinterpret_cast<float2*>(&out[(size_t)(row0 + 8) * N_OUT + col]) = v1;
        }
    }
}

// ---------------------------------------------------------------------------
extern "C" void kernel_launch(void* const* d_in, const int* in_sizes, int n_in,
                              void* d_out, int out_size)
{
    const int*   X     = (const int*)  d_in[0];
    const float* h0    = (const float*)d_in[1];
    const float* W_ih  = (const float*)d_in[2];
    const float* b_ih  = (const float*)d_in[3];
    const float* W_hh  = (const float*)d_in[4];
    const float* b_hh  = (const float*)d_in[5];
    const float* W_out = (const float*)d_in[6];
    const float* b_out = (const float*)d_in[7];

    float* out = (float*)d_out;
    float* hlast = (out_size >= M_OUT * N_OUT + BATCH * HIDDEN)
                       ? out + (size_t)M_OUT * N_OUT
                       : nullptr;

    // >48KB dynamic smem needs the attribute (idempotent, capture-safe).
    cudaFuncSetAttribute(rnn_recurrence,
                         cudaFuncAttributeMaxDynamicSharedMemorySize, SM_TOTAL);

    rnn_recurrence<<<BATCH, 1024, SM_TOTAL>>>(X, h0, W_ih, b_ih, W_hh, b_hh, hlast);

    dim3 grid(N_OUT / BN, M_OUT / BM);  // 125 x 64
    out_gemm<<<grid, 256>>>(W_out, b_out, out);
}

// round 11
// speedup vs baseline: 5.1075x; 1.1677x over previous
#include <cuda_runtime.h>
#include <cuda_fp16.h>
#include <cuda_bf16.h>
#include <cstdint>

#define VOCAB  8000
#define HIDDEN 256
#define BATCH  32
#define SEQ    256
#define M_OUT  (SEQ*BATCH)      // 8192
#define N_OUT  VOCAB            // 8000
#define K_OUT  HIDDEN           // 256

// Scratch: Y (seq, batch, hidden) hidden states, stored fp16 for the GEMM (4 MB).
__device__ __half g_Yh[(size_t)SEQ * BATCH * HIDDEN];

// ---------------------------------------------------------------------------
// Kernel 1: recurrence. ONE CTA per batch element. R11 hybrid W placement:
// each thread (j = output row, s = 64-wide k-slice) keeps its first 32
// weights in fp32 REGISTERS (32 regs x 1024 thr = half the RF) and reads the
// other 32 from fp16 smem (68 KB). This halves the per-step smem-crossbar
// traffic (R10's real floor: lane-divergent W LDS = 4 cyc each, 128 KB/step)
// and cuts the F2F convert count 4x. fp32 h state + fp32 accumulation.
// ---------------------------------------------------------------------------
#define WHI_STRIDE 136                        // halves/row = 17 quads (odd -> conflict-free)
#define SM_WHI_BYTES (HIDDEN * WHI_STRIDE * 2)  // 69632
#define SM_H_OFF   SM_WHI_BYTES
#define SM_P_OFF   (SM_H_OFF + 2 * HIDDEN * 4)
#define SM_TOTAL   (SM_P_OFF + 3 * HIDDEN * 4)   // 74752 B

__global__ __launch_bounds__(1024, 1)
void rnn_recurrence(const int* __restrict__ X,
                    const float* __restrict__ h0,
                    const float* __restrict__ W_ih,
                    const float* __restrict__ b_ih,
                    const float* __restrict__ W_hh,
                    const float* __restrict__ b_hh,
                    float* __restrict__ hlast)   // may be null
{
    extern __shared__ char dyn[];
    __half* Whi  = reinterpret_cast<__half*>(dyn);            // [256][136]
    float*  hbuf = reinterpret_cast<float*>(dyn + SM_H_OFF);  // [2][256]
    float*  part = reinterpret_cast<float*>(dyn + SM_P_OFF);  // [3][256]

    const int tid = threadIdx.x;
    const int b   = blockIdx.x;

    const int w    = tid >> 5;
    const int lane = tid & 31;
    const int s    = w >> 3;                 // k-slice 0..3 (64 k each)
    const int j    = ((w & 7) << 5) + lane;  // output row 0..255

    // One-time: W-hi (k = s*64+32 .. s*64+63 for every (j,s)) -> fp16 smem.
    // Element (j, c) with c = s*32+i maps to W_hh[j*256 + s*64 + 32 + i].
    for (int e = tid; e < HIDDEN * 128; e += 1024) {
        const int jj = e >> 7, c = e & 127;
        const int ss = c >> 5, ii = c & 31;
        Whi[jj * WHI_STRIDE + c] =
            __float2half(W_hh[jj * HIDDEN + ss * 64 + 32 + ii]);
    }
    // One-time: W-lo (k = s*64 .. s*64+31) -> fp32 registers.
    float4 Wlo[8];
    {
        const float4* wg =
            reinterpret_cast<const float4*>(W_hh + (size_t)j * HIDDEN + s * 64);
        #pragma unroll
        for (int q = 0; q < 8; ++q) Wlo[q] = wg[q];
    }
    if (tid < HIDDEN) hbuf[tid] = h0[b * HIDDEN + tid];   // buffer 0

    float bias = 0.f;
    if (s == 0) bias = b_ih[j] + b_hh[j];
    const float* __restrict__ wih_row = W_ih + (size_t)j * VOCAB;
    const int*   __restrict__ xrow    = X + b * SEQ;
    __syncthreads();

    const uint4* __restrict__ whv =
        reinterpret_cast<const uint4*>(Whi + j * WHI_STRIDE + s * 32);  // 4 quads

    int p = 0;
    int idx = xrow[0];
    for (int t = 0; t < SEQ; ++t) {
        float xg = 0.f;
        if (s == 0) xg = __ldg(wih_row + idx);   // gather, consumed at tanh

        const float4* hlo =
            reinterpret_cast<const float4*>(hbuf + p * HIDDEN + s * 64);
        float a0 = 0.f, a1 = 0.f, a2 = 0.f, a3 = 0.f;

        // k-lo: register weights
        #pragma unroll
        for (int q = 0; q < 8; ++q) {
            const float4 h4 = hlo[q];            // warp-uniform broadcast
            a0 = fmaf(Wlo[q].x, h4.x, a0);
            a1 = fmaf(Wlo[q].y, h4.y, a1);
            a2 = fmaf(Wlo[q].z, h4.z, a2);
            a3 = fmaf(Wlo[q].w, h4.w, a3);
        }
        // k-hi: fp16 smem weights
        #pragma unroll
        for (int q = 0; q < 4; ++q) {
            const uint4  wq = whv[q];            // 8 fp16 weights
            const float4 hA = hlo[8 + 2 * q];
            const float4 hB = hlo[8 + 2 * q + 1];
            const float2 w01 = __half22float2(*reinterpret_cast<const __half2*>(&wq.x));
            const float2 w23 = __half22float2(*reinterpret_cast<const __half2*>(&wq.y));
            const float2 w45 = __half22float2(*reinterpret_cast<const __half2*>(&wq.z));
            const float2 w67 = __half22float2(*reinterpret_cast<const __half2*>(&wq.w));
            a0 = fmaf(w01.x, hA.x, a0); a1 = fmaf(w01.y, hA.y, a1);
            a2 = fmaf(w23.x, hA.z, a2); a3 = fmaf(w23.y, hA.w, a3);
            a0 = fmaf(w45.x, hB.x, a0); a1 = fmaf(w45.y, hB.y, a1);
            a2 = fmaf(w67.x, hB.z, a2); a3 = fmaf(w67.y, hB.w, a3);
        }
        float acc = (a0 + a1) + (a2 + a3);
        if (t + 1 < SEQ) idx = xrow[t + 1];

        if (s) part[((s - 1) << 8) + j] = acc;
        __syncthreads();
        if (s == 0) {
            const float hn = tanhf(xg + bias + acc +
                                   part[j] + part[256 + j] + part[512 + j]);
            hbuf[(p ^ 1) * HIDDEN + j] = hn;
            g_Yh[((size_t)t * BATCH + b) * HIDDEN + j] = __float2half(hn);
        }
        __syncthreads();
        p ^= 1;
    }
    if (s == 0 && hlast) hlast[b * HIDDEN + j] = hbuf[p * HIDDEN + j];
}

// ---------------------------------------------------------------------------
// Kernel 2: out = Y @ W_out^T + b_out via fp16 mma.sync m16n8k16, fp32 accum.
// UNCHANGED from R10 (isolating the recurrence change). L1 83.7% is its cap;
// next round: tcgen05 SS-mode to eliminate fragment smem traffic.
// ---------------------------------------------------------------------------
__device__ __forceinline__ void mma_f16(float& d0, float& d1, float& d2, float& d3,
                                        unsigned a0, unsigned a1, unsigned a2, unsigned a3,
                                        unsigned b0, unsigned b1)
{
    asm volatile(
        "mma.sync.aligned.m16n8k16.row.col.f32.f16.f16.f32 "
        "{%0,%1,%2,%3}, {%4,%5,%6,%7}, {%8,%9}, {%0,%1,%2,%3};\n"
        : "+f"(d0), "+f"(d1), "+f"(d2), "+f"(d3)
        : "r"(a0), "r"(a1), "r"(a2), "r"(a3), "r"(b0), "r"(b1));
}

#define BM 128
#define BN 64
#define BK 32          // k elements per stage
#define S2 20          // row stride in half2 units (BK/2 + 4 pad)

__global__ __launch_bounds__(256, 3)
void out_gemm(const float* __restrict__ W_out,
              const float* __restrict__ b_out,
              float* __restrict__ out)
{
    __shared__ __half2 As[BM * S2];   // 10240 B
    __shared__ __half2 Bs[BN * S2];   //  5120 B

    const int tid  = threadIdx.x;
    const int lane = tid & 31;
    const int warp = tid >> 5;
    const int g = lane >> 2;       // group id 0..7
    const int t = lane & 3;        // thread-in-group 0..3
    const int warpM = warp >> 1;   // 0..3
    const int warpN = warp & 1;    // 0..1
    const int mbase = warpM * 32;
    const int nbase = warpN * 32;

    const int bn = blockIdx.x;     // 0..124
    const int bm = blockIdx.y;     // 0..63

    float acc[2][4][4];
    #pragma unroll
    for (int mi = 0; mi < 2; ++mi)
        #pragma unroll
        for (int ni = 0; ni < 4; ++ni)
            #pragma unroll
            for (int c = 0; c < 4; ++c) acc[mi][ni][c] = 0.f;

    const __half* Abase = g_Yh + (size_t)(bm * BM) * K_OUT;   // row-major 8192x256
    const float*  Bbase = W_out + (size_t)(bn * BN) * K_OUT;  // row-major 8000x256

    // staging maps
    const int aq = tid & 3;        // 4 uint4 (32 halves) per A row
    const int ar = tid >> 2;       // 0..63 -> rows ar, ar+64
    const int bc = tid & 7;        // 8 float4 per B row
    const int br = tid >> 3;       // 0..31 -> rows br, br+32

    // prologue: prefetch tile kc=0 into registers
    uint4  ra[2];
    float4 rb[2];
    {
        #pragma unroll
        for (int i = 0; i < 2; ++i)
            ra[i] = *reinterpret_cast<const uint4*>(
                Abase + (size_t)(ar + i * 64) * K_OUT + aq * 8);
        #pragma unroll
        for (int i = 0; i < 2; ++i)
            rb[i] = *reinterpret_cast<const float4*>(
                Bbase + (size_t)(br + i * 32) * K_OUT + bc * 4);
    }

    for (int kc = 0; kc < K_OUT; kc += BK) {
        // ---- commit staged registers to smem
        #pragma unroll
        for (int i = 0; i < 2; ++i)
            *reinterpret_cast<uint4*>(&As[(ar + i * 64) * S2 + aq * 4]) = ra[i];
        #pragma unroll
        for (int i = 0; i < 2; ++i) {
            __half2 h01 = __floats2half2_rn(rb[i].x, rb[i].y);
            __half2 h23 = __floats2half2_rn(rb[i].z, rb[i].w);
            uint2 u;
            u.x = *reinterpret_cast<unsigned*>(&h01);
            u.y = *reinterpret_cast<unsigned*>(&h23);
            *reinterpret_cast<uint2*>(&Bs[(br + i * 32) * S2 + bc * 2]) = u;
        }
        __syncthreads();

        // ---- prefetch NEXT tile (overlaps the MMA section)
        if (kc + BK < K_OUT) {
            #pragma unroll
            for (int i = 0; i < 2; ++i)
                ra[i] = *reinterpret_cast<const uint4*>(
                    Abase + (size_t)(ar + i * 64) * K_OUT + kc + BK + aq * 8);
            #pragma unroll
            for (int i = 0; i < 2; ++i)
                rb[i] = *reinterpret_cast<const float4*>(
                    Bbase + (size_t)(br + i * 32) * K_OUT + kc + BK + bc * 4);
        }

        // ---- 2 k16 steps per stage
        #pragma unroll
        for (int ko = 0; ko < BK / 2; ko += 8) {
            unsigned a[2][4];
            #pragma unroll
            for (int mi = 0; mi < 2; ++mi) {
                const int r0 = (mbase + mi * 16 + g) * S2 + ko + t;
                const int r1 = (mbase + mi * 16 + 8 + g) * S2 + ko + t;
                a[mi][0] = *reinterpret_cast<const unsigned*>(&As[r0]);
                a[mi][1] = *reinterpret_cast<const unsigned*>(&As[r1]);
                a[mi][2] = *reinterpret_cast<const unsigned*>(&As[r0 + 4]);
                a[mi][3] = *reinterpret_cast<const unsigned*>(&As[r1 + 4]);
            }
            unsigned bf[4][2];
            #pragma unroll
            for (int ni = 0; ni < 4; ++ni) {
                const int r = (nbase + ni * 8 + g) * S2 + ko + t;
                bf[ni][0] = *reinterpret_cast<const unsigned*>(&Bs[r]);
                bf[ni][1] = *reinterpret_cast<const unsigned*>(&Bs[r + 4]);
            }
            #pragma unroll
            for (int mi = 0; mi < 2; ++mi)
                #pragma unroll
                for (int ni = 0; ni < 4; ++ni)
                    mma_f16(acc[mi][ni][0], acc[mi][ni][1],
                            acc[mi][ni][2], acc[mi][ni][3],
                            a[mi][0], a[mi][1], a[mi][2], a[mi][3],
                            bf[ni][0], bf[ni][1]);
        }
        __syncthreads();
    }

    // ---- epilogue: add bias, store (float2, cols 2t/2t+1 contiguous)
    #pragma unroll
    for (int ni = 0; ni < 4; ++ni) {
        const int col = bn * BN + nbase + ni * 8 + 2 * t;
        const float2 bv = *reinterpret_cast<const float2*>(&b_out[col]);
        #pragma unroll
        for (int mi = 0; mi < 2; ++mi) {
            const int row0 = bm * BM + mbase + mi * 16 + g;
            float2 v0; v0.x = acc[mi][ni][0] + bv.x; v0.y = acc[mi][ni][1] + bv.y;
            float2 v1; v1.x = acc[mi][ni][2] + bv.x; v1.y = acc[mi][ni][3] + bv.y;
            *reinterpret_cast<float2*>(&out[(size_t)row0 * N_OUT + col]) = v0;
            *reinterpret_cast<float2*>(&out[(size_t)(row0 + 8) * N_OUT + col]) = v1;
        }
    }
}

// ---------------------------------------------------------------------------
extern "C" void kernel_launch(void* const* d_in, const int* in_sizes, int n_in,
                              void* d_out, int out_size)
{
    const int*   X     = (const int*)  d_in[0];
    const float* h0    = (const float*)d_in[1];
    const float* W_ih  = (const float*)d_in[2];
    const float* b_ih  = (const float*)d_in[3];
    const float* W_hh  = (const float*)d_in[4];
    const float* b_hh  = (const float*)d_in[5];
    const float* W_out = (const float*)d_in[6];
    const float* b_out = (const float*)d_in[7];

    float* out = (float*)d_out;
    float* hlast = (out_size >= M_OUT * N_OUT + BATCH * HIDDEN)
                       ? out + (size_t)M_OUT * N_OUT
                       : nullptr;

    // >48KB dynamic smem needs the attribute (idempotent, capture-safe).
    cudaFuncSetAttribute(rnn_recurrence,
                         cudaFuncAttributeMaxDynamicSharedMemorySize, SM_TOTAL);

    rnn_recurrence<<<BATCH, 1024, SM_TOTAL>>>(X, h0, W_ih, b_ih, W_hh, b_hh, hlast);

    dim3 grid(N_OUT / BN, M_OUT / BM);  // 125 x 64
    out_gemm<<<grid, 256>>>(W_out, b_out, out);
}